// round 10
// baseline (speedup 1.0000x reference)
#include <cuda_runtime.h>
#include <cuda_fp16.h>

#define BIG 1e9f
#define FULLMASK 0xFFFFFFFFu

// One warp per image, 4 images per 128-thread block (4 warps -> all 4 SMSPs,
// since SMSP = wid % 4 within the block; 2-warp blocks left SMSP 2,3 idle).
// Lane l owns rows 2l, 2l+1. Anti-diagonal wavefront t = i+j = 1..126 with
// potential transform z = d + img/2:  z[i][j] = img[i][j] + min(zL, zU, zD).
// Image staged to smem as fp16 (z math fp32). Even rows in sA, odd in sB,
// row stride 68 halfwords -> wavefront LDS word = 33*l + f(t): conflict-free.
// Out-of-window cells carry ~1e9 and never win a min; all indices statically
// in-bounds across the two arrays (no clamping, no NaN).
__global__ void __launch_bounds__(128) dp_wavefront_kernel(
    const float* __restrict__ img, float* __restrict__ out, int B)
{
    __shared__ __half smem[4][2 * 32 * 68];      // per image: sA[32][68], sB[32][68]

    const int w = threadIdx.x >> 5;               // warp in block: 0..3
    const int lane = threadIdx.x & 31;
    const int img_idx = blockIdx.x * 4 + w;
    if (img_idx >= B) return;                     // warp-uniform

    __half* sA = smem[w];
    __half* sB = smem[w] + 32 * 68;

    // ---- stage image: float4 LDG -> packed half2 STS (row stride 68 halves) ----
    {
        const float4* g4 = reinterpret_cast<const float4*>(img + (size_t)img_idx * 4096);
        __half* base = (lane < 16) ? sA : sB;     // lanes 0-15: even rows; 16-31: odd
        const int s = lane & 15;                  // column group (4 floats)
        #pragma unroll 4
        for (int k = 0; k < 32; k++) {
            float4 v = g4[k * 32 + lane];         // element (row 2k+(lane>=16), col 4s..)
            __half2* d2 = reinterpret_cast<__half2*>(base + 68 * k + 4 * s);
            d2[0] = __floats2half2_rn(v.x, v.y);
            d2[1] = __floats2half2_rn(v.z, v.w);
        }
        __syncwarp();
    }

    // xA(t) = img[2l][t-2l]     = sA[68l + t-2l]   = pA[t],  pA = sA + 66l
    // xB(t) = img[2l+1][t-2l-1] = sB[68l + t-2l-1] = pB[t],  pB = sB + 66l - 1
    const __half* pA = sA + 66 * lane;
    const __half* pB = sB + 66 * lane - 1;        // first deref is pB[1] >= sB[0]

    // state: zA1/zA2 = own A at t-1/t-2; zB1 = own B at t-1; zL2 = left B at t-2
    float zA1 = (lane == 0) ? 0.5f * __half2float(sA[0]) : BIG;
    float zA2 = BIG;
    float zB1 = BIG;
    float zL2 = BIG;

    // prefetched image values for step t=1
    float xA = __half2float(pA[1]);
    float xB = __half2float(pB[1]);

    #pragma unroll 4
    for (int t = 1; t <= 126; t++) {
        float zL1 = __shfl_up_sync(FULLMASK, zB1, 1);    // left-lane B at t-1
        if (lane == 0) zL1 = BIG;                         // row -1 doesn't exist

        // prefetch for t+1 (immediate offsets after unroll; max index in-bounds)
        float nA = __half2float(pA[t + 1]);
        float nB = __half2float(pB[t + 1]);

        float zAnew = xA + fminf(fminf(zA1, zL1), zL2);
        float zBnew = xB + fminf(zB1, fminf(zA1, zA2));

        zA2 = zA1; zA1 = zAnew;
        zB1 = zBnew;
        zL2 = zL1;
        xA = nA; xB = nB;
    }

    // d[63][63] = z[63][63] - 0.5*img[63][63]; (63,63) is lane 31's B cell = pB[126]
    if (lane == 31) out[img_idx] = zB1 - 0.5f * __half2float(pB[126]);
}

extern "C" void kernel_launch(void* const* d_in, const int* in_sizes, int n_in,
                              void* d_out, int out_size) {
    const float* img = (const float*)d_in[0];
    float* out = (float*)d_out;
    int B = in_sizes[0] / (64 * 64);
    int blocks = (B + 3) / 4;            // 4 images per 128-thread block
    dp_wavefront_kernel<<<blocks, 128>>>(img, out, B);
}

// round 11
// speedup vs baseline: 1.1224x; 1.1224x over previous
#include <cuda_runtime.h>
#include <cuda_fp16.h>

#define BIG 1e9f
#define FULLMASK 0xFFFFFFFFu

// One warp per image, 2 images per 64-thread block (1024 blocks -> 6.9/SM,
// best tail balance). Lane l owns rows 2l, 2l+1. Wavefront t=i+j=1..126,
// potential transform z = d + img/2: z[i][j] = img[i][j] + min(zL, zU, zD).
// fp16 image in smem; even rows sA, odd rows sB, row stride 68 halfwords.
// Scalar access index for both streams is 66l + t; at even t that's half2-
// aligned and word 33l+t/2 -> bank (l + t/2) mod 32: conflict-free. One
// half2 LDS per row per TWO steps. Out-of-window cells carry ~1e9 and never
// win a min; all indices statically in-bounds (no clamps, no NaN).
__global__ void __launch_bounds__(64) dp_wavefront_kernel(
    const float* __restrict__ img, float* __restrict__ out, int B)
{
    __shared__ __half smem[2][2 * 32 * 68];      // per image: sA[32][68], sB[32][68]

    const int w = threadIdx.x >> 5;
    const int lane = threadIdx.x & 31;
    const int img_idx = blockIdx.x * 2 + w;
    if (img_idx >= B) return;                     // warp-uniform

    __half* sA = smem[w];
    __half* sB = smem[w] + 32 * 68;

    // ---- stage image: float4 LDG (MLP=16) -> packed half2 STS ----
    {
        const float4* g4 = reinterpret_cast<const float4*>(img + (size_t)img_idx * 4096);
        __half* base = (lane < 16) ? sA : sB;     // lanes 0-15: even rows; 16-31: odd
        const int s = lane & 15;
        #pragma unroll
        for (int h = 0; h < 2; h++) {             // two MLP-16 batches
            float4 v[16];
            #pragma unroll
            for (int k = 0; k < 16; k++)
                v[k] = g4[(h * 16 + k) * 32 + lane];
            #pragma unroll
            for (int k = 0; k < 16; k++) {
                __half2* d2 = reinterpret_cast<__half2*>(base + 68 * (h * 16 + k) + 4 * s);
                d2[0] = __floats2half2_rn(v[k].x, v[k].y);
                d2[1] = __floats2half2_rn(v[k].z, v[k].w);
            }
        }
        __syncwarp();
    }

    // A stream: xA(t) = sA[66l + t]; B stream: xB(t) = sB[66l + t - 1].
    // half2 word pointers at the same word index 33l + k cover:
    //   A: (xA(2k), xA(2k+1))     B: (xB(2k+1), xB(2k+2))
    const __half2* qA = reinterpret_cast<const __half2*>(sA) + 33 * lane;
    const __half2* qB = reinterpret_cast<const __half2*>(sB) + 33 * lane;

    // state
    float zA1 = (lane == 0) ? 0.5f * __half2float(sA[0]) : BIG;
    float zA2 = BIG;
    float zB1 = BIG;
    float zL2 = BIG;

    // prologue values: t=1 scalars + carried xB(2) from B-pair k=0
    float xA1 = __half2float(sA[66 * lane + 1]);
    float2 b0 = __half22float2(qB[0]);            // xB(1), xB(2)
    float xB1 = b0.x;
    float xBc = b0.y;                             // carried xB(2k) for next iter

    // ---- step t = 1 ----
    {
        float zL1 = __shfl_up_sync(FULLMASK, zB1, 1);
        if (lane == 0) zL1 = BIG;
        float zAn = xA1 + fminf(fminf(zA1, zL1), zL2);
        float zBn = xB1 + fminf(zB1, fminf(zA1, zA2));
        zA2 = zA1; zA1 = zAn; zB1 = zBn; zL2 = zL1;
    }

    // ---- steps t = 2k, 2k+1 for k = 1..62 ----
    #pragma unroll 2
    for (int k = 1; k <= 62; k++) {
        float2 av = __half22float2(qA[k]);        // xA(2k), xA(2k+1)
        float2 bv = __half22float2(qB[k]);        // xB(2k+1), xB(2k+2)
        float xB0 = xBc;                          // xB(2k)
        xBc = bv.y;

        // step t = 2k
        float zL1 = __shfl_up_sync(FULLMASK, zB1, 1);
        if (lane == 0) zL1 = BIG;
        float zAn = av.x + fminf(fminf(zA1, zL1), zL2);
        float zBn = xB0 + fminf(zB1, fminf(zA1, zA2));
        zA2 = zA1; zA1 = zAn; zB1 = zBn; zL2 = zL1;

        // step t = 2k+1
        zL1 = __shfl_up_sync(FULLMASK, zB1, 1);
        if (lane == 0) zL1 = BIG;
        zAn = av.y + fminf(fminf(zA1, zL1), zL2);
        zBn = bv.x + fminf(zB1, fminf(zA1, zA2));
        zA2 = zA1; zA1 = zAn; zB1 = zBn; zL2 = zL1;
    }

    // ---- step t = 126 (only B cell matters for the answer path) ----
    {
        float zBn = xBc + fminf(zB1, fminf(zA1, zA2));   // xBc = xB(126)
        zB1 = zBn;
    }

    // d[63][63] = z[63][63] - 0.5*img[63][63]; (63,63) is lane 31's B cell
    if (lane == 31) out[img_idx] = zB1 - 0.5f * __half2float(sB[66 * 31 + 125]);

}

extern "C" void kernel_launch(void* const* d_in, const int* in_sizes, int n_in,
                              void* d_out, int out_size) {
    const float* img = (const float*)d_in[0];
    float* out = (float*)d_out;
    int B = in_sizes[0] / (64 * 64);
    int blocks = (B + 1) / 2;            // 2 images per 64-thread block
    dp_wavefront_kernel<<<blocks, 64>>>(img, out, B);
}

// round 13
// speedup vs baseline: 1.1677x; 1.0404x over previous
#include <cuda_runtime.h>
#include <cuda_fp16.h>

#define BIG 1e9f
#define FULLMASK 0xFFFFFFFFu

// 32-thread blocks, TWO images per warp: lanes 0-15 -> image 2b, 16-31 -> 2b+1.
// Each lane owns 4 rows (4sl..4sl+3): cells A,B,C,D on wavefront t=i+j=1..126.
// Potential transform z = d + img/2: z[i][j] = img[i][j] + min(zL, zU, zD).
// Cross-lane dependency only A<-left D (width-16 shfl, 1 per step, serves both
// images). fp16 image in smem; per image chunk: [sA 32x68][sB 32x68][pad 2]
// halves = 2177 words (odd) -> image0 lanes hit even banks, image1 odd banks:
// every LDS/STS conflict-free. Row streams per lane (scalar idx base 132*sl):
//   xA(t)=sA[132sl+t]  xB(t)=sB[132sl+t-1]  xC(t)=sA[132sl+t+66]  xD(t)=sB[132sl+t+65]
// half2 words: wA[k]=(xA(2k),xA(2k+1)) wC[k]=(xC(2k),xC(2k+1))
//              wB[k]=(xB(2k+1),xB(2k+2)) wD[k]=(xD(2k+1),xD(2k+2))  (carry xB/xD(2k))
// Out-of-window cells carry ~1e9 and never win a min. Row padding halves are
// zeroed so out-of-window stream reads are finite (never NaN/-inf).
__global__ void __launch_bounds__(32) dp_wavefront_kernel(
    const float* __restrict__ img, float* __restrict__ out, int B)
{
    __shared__ __half smem[2][4354];            // 2 image chunks, odd word stride

    const int lane = threadIdx.x;               // 0..31
    const int sl = lane & 15;
    int img_idx = blockIdx.x * 2 + (lane >> 4);
    const bool valid = (img_idx < B);
    if (!valid) img_idx = B - 1;                // keep lanes resident for shfl

    __half* sA = smem[lane >> 4];
    __half* sB = sA + 2176;

    // ---- zero row padding (scalars [68m+64, 68m+68) of both arrays) ----
    {
        __half2* a2 = reinterpret_cast<__half2*>(sA);
        __half2* b2 = reinterpret_cast<__half2*>(sB);
        const __half2 z2 = __floats2half2_rn(0.f, 0.f);
        #pragma unroll
        for (int m = sl; m < 32; m += 16) {
            a2[34 * m + 32] = z2; a2[34 * m + 33] = z2;
            b2[34 * m + 32] = z2; b2[34 * m + 33] = z2;
        }
    }

    // ---- stage own image: each half-warp loads its image, fp32->fp16 ----
    {
        const float4* g4 = reinterpret_cast<const float4*>(img + (size_t)img_idx * 4096);
        #pragma unroll
        for (int h = 0; h < 4; h++) {           // 4 batches of MLP-16
            float4 v[16];
            #pragma unroll
            for (int k = 0; k < 16; k++)
                v[k] = g4[(h * 16 + k) * 16 + sl];      // row h*16+k, cols 4sl..4sl+3
            #pragma unroll
            for (int k = 0; k < 16; k++) {
                int r = h * 16 + k;
                __half* dst = ((r & 1) ? sB : sA) + 68 * (r >> 1) + 4 * sl;
                reinterpret_cast<__half2*>(dst)[0] = __floats2half2_rn(v[k].x, v[k].y);
                reinterpret_cast<__half2*>(dst)[1] = __floats2half2_rn(v[k].z, v[k].w);
            }
        }
        __syncwarp();
    }

    const __half2* wA = reinterpret_cast<const __half2*>(sA) + 66 * sl;
    const __half2* wC = wA + 33;
    const __half2* wB = reinterpret_cast<const __half2*>(sB) + 66 * sl;
    const __half2* wD = wB + 33;

    // ---- prologue: t = 1 ----
    float2 a0 = __half22float2(wA[0]);          // xA(0), xA(1)
    float2 b0 = __half22float2(wB[0]);          // xB(1), xB(2)
    float2 c0 = __half22float2(wC[0]);          // xC(0), xC(1)
    float2 d0 = __half22float2(wD[0]);          // xD(1), xD(2)

    float zA1 = (sl == 0) ? 0.5f * a0.x : BIG;  // z(0,0) at lane 0's A
    float zA2 = BIG, zB1 = BIG, zB2 = BIG, zC1 = BIG, zC2 = BIG, zD1 = BIG, zL2 = BIG;

    {
        float zLa = __shfl_up_sync(FULLMASK, zD1, 1, 16);
        if (sl == 0) zLa = BIG;
        float zAn = a0.y + fminf(fminf(zA1, zLa), zL2);
        float zBn = b0.x + fminf(zB1, fminf(zA1, zA2));
        float zCn = c0.y + fminf(zC1, fminf(zB1, zB2));
        float zDn = d0.x + fminf(zD1, fminf(zC1, zC2));
        zA2 = zA1; zA1 = zAn; zB2 = zB1; zB1 = zBn;
        zC2 = zC1; zC1 = zCn; zD1 = zDn; zL2 = zLa;
    }
    float bc = b0.y, dc = d0.y;                 // carried xB(2), xD(2)

    // ---- pairs t = (2k, 2k+1), k = 1..62 ----
    #pragma unroll 2
    for (int k = 1; k <= 62; k++) {
        float2 av = __half22float2(wA[k]);      // xA(2k), xA(2k+1)
        float2 cv = __half22float2(wC[k]);      // xC(2k), xC(2k+1)
        float2 bv = __half22float2(wB[k]);      // xB(2k+1), xB(2k+2)
        float2 dv = __half22float2(wD[k]);      // xD(2k+1), xD(2k+2)
        float xB0 = bc; bc = bv.y;
        float xD0 = dc; dc = dv.y;

        // step t = 2k
        float zLa = __shfl_up_sync(FULLMASK, zD1, 1, 16);
        if (sl == 0) zLa = BIG;
        float zAn = av.x + fminf(fminf(zA1, zLa), zL2);
        float zBn = xB0 + fminf(zB1, fminf(zA1, zA2));
        float zCn = cv.x + fminf(zC1, fminf(zB1, zB2));
        float zDn = xD0 + fminf(zD1, fminf(zC1, zC2));
        zA2 = zA1; zA1 = zAn; zB2 = zB1; zB1 = zBn;
        zC2 = zC1; zC1 = zCn; zD1 = zDn; zL2 = zLa;

        // step t = 2k+1
        float zLb = __shfl_up_sync(FULLMASK, zD1, 1, 16);
        if (sl == 0) zLb = BIG;
        zAn = av.y + fminf(fminf(zA1, zLb), zL2);
        zBn = bv.x + fminf(zB1, fminf(zA1, zA2));
        zCn = cv.y + fminf(zC1, fminf(zB1, zB2));
        zDn = dv.x + fminf(zD1, fminf(zC1, zC2));
        zA2 = zA1; zA1 = zAn; zB2 = zB1; zB1 = zBn;
        zC2 = zC1; zC1 = zCn; zD1 = zDn; zL2 = zLb;
    }

    // ---- t = 126: only the D cell feeds the answer ----
    float zDfin = dc + fminf(zD1, fminf(zC1, zC2));   // dc = xD(126) = img[63][63]

    // d[63][63] = z - 0.5*img[63][63]; (63,63) is lane sl=15's D cell
    if (sl == 15 && valid) out[img_idx] = zDfin - 0.5f * dc;
}

extern "C" void kernel_launch(void* const* d_in, const int* in_sizes, int n_in,
                              void* d_out, int out_size) {
    const float* img = (const float*)d_in[0];
    float* out = (float*)d_out;
    int B = in_sizes[0] / (64 * 64);
    int blocks = (B + 1) / 2;            // 2 images per 32-thread block (1 warp)
    dp_wavefront_kernel<<<blocks, 32>>>(img, out, B);
}